// round 5
// baseline (speedup 1.0000x reference)
#include <cuda_runtime.h>
#include <math.h>

#define D_DIM 3072
#define C_DIM 10
#define B_DIM 4096
#define R_ROWS 2                           // rows per warp
#define QUARTERS 4
#define D_Q (D_DIM / QUARTERS)             // 768
#define XV (D_Q / 128)                     // 6 float4 per row per lane
#define WARPS 8
#define BLOCK (WARPS * 32)                 // 256
#define ROWS_PER_BLOCK 4                   // 2 row-pairs x 4 quarters = 8 warps
#define GRIDM (B_DIM / ROWS_PER_BLOCK)     // 1024 blocks

#define EPS_REG 0.1f
#define NUM_STAB 1e-6f

// scratch (no cudaMalloc allowed)
__device__ __align__(16) float g_Wt[C_DIM * D_DIM];   // W transposed [C][D]
__device__ float g_M[C_DIM * C_DIM];                  // M = W^T W
__device__ float g_partials[GRIDM];
__device__ unsigned int g_count = 0;                  // reset by last block each call

// ---------------------------------------------------------------------------
// Prep: 120 blocks x 256 threads. Coalesced-read / scattered-write transpose
// of W into g_Wt. Blocks 0..99 also compute one entry of M = W^T W each.
// ---------------------------------------------------------------------------
__global__ __launch_bounds__(256) void prep_kernel(const float* __restrict__ W) {
    const int idx = blockIdx.x * 256 + threadIdx.x;      // < 30720 always
    {
        // coalesced read W[idx] (layout [D][C]), scattered write to g_Wt [C][D]
        int d = idx / C_DIM;
        int j = idx - d * C_DIM;
        g_Wt[j * D_DIM + d] = W[idx];
    }
    if (blockIdx.x >= C_DIM * C_DIM) return;

    const int j1 = blockIdx.x / C_DIM;
    const int j2 = blockIdx.x % C_DIM;

    float partial = 0.f;
    #pragma unroll 4
    for (int d = threadIdx.x; d < D_DIM; d += 256)
        partial = fmaf(W[d * C_DIM + j1], W[d * C_DIM + j2], partial);

    #pragma unroll
    for (int off = 16; off; off >>= 1)
        partial += __shfl_xor_sync(0xffffffffu, partial, off);

    __shared__ float sw[8];
    int lane = threadIdx.x & 31, w = threadIdx.x >> 5;
    if (lane == 0) sw[w] = partial;
    __syncthreads();
    if (threadIdx.x == 0) {
        float s = 0.f;
        #pragma unroll
        for (int k = 0; k < 8; k++) s += sw[k];
        g_M[blockIdx.x] = s;
    }
}

// ---------------------------------------------------------------------------
// Main: warp = (row-pair, D-quarter). Full x tile front-batched into registers
// (12 outstanding LDG.128 per warp), plain f32 accumulators, W via L1.
// Quarters combined in smem; analytic epilogue; fused final reduction.
// ---------------------------------------------------------------------------
__global__ __launch_bounds__(BLOCK, 2) void main_kernel(const float* __restrict__ data,
                                                        float* __restrict__ out) {
    __shared__ float sM[C_DIM * C_DIM];
    __shared__ float sAcc[WARPS][R_ROWS * C_DIM];
    __shared__ float sWarpSum[WARPS];
    __shared__ bool  sIsLast;

    const int warpId  = threadIdx.x >> 5;
    const int lane    = threadIdx.x & 31;
    const int rp      = warpId & 1;          // row-pair within block
    const int quarter = warpId >> 1;         // D quarter
    const int row0    = blockIdx.x * ROWS_PER_BLOCK + rp * R_ROWS;

    const float* xbase = data + (size_t)row0 * D_DIM + quarter * D_Q + lane * 4;
    const float* wbase = g_Wt + quarter * D_Q + lane * 4;

    // --- front-batch the whole x tile: 12 independent LDG.128 in flight ---
    float4 xa[XV], xb[XV];
    #pragma unroll
    for (int i = 0; i < XV; i++)
        xa[i] = __ldcs(reinterpret_cast<const float4*>(xbase + i * 128));
    #pragma unroll
    for (int i = 0; i < XV; i++)
        xb[i] = __ldcs(reinterpret_cast<const float4*>(xbase + D_DIM + i * 128));

    if (threadIdx.x < C_DIM * C_DIM) sM[threadIdx.x] = g_M[threadIdx.x];

    float acc0[C_DIM], acc1[C_DIM];
    #pragma unroll
    for (int j = 0; j < C_DIM; j++) { acc0[j] = 0.f; acc1[j] = 0.f; }

    #pragma unroll
    for (int it = 0; it < XV; it++) {
        #pragma unroll
        for (int j = 0; j < C_DIM; j++) {
            float4 wf = *reinterpret_cast<const float4*>(wbase + j * D_DIM + it * 128);
            acc0[j] = fmaf(xa[it].x, wf.x, acc0[j]);
            acc0[j] = fmaf(xa[it].y, wf.y, acc0[j]);
            acc0[j] = fmaf(xa[it].z, wf.z, acc0[j]);
            acc0[j] = fmaf(xa[it].w, wf.w, acc0[j]);
            acc1[j] = fmaf(xb[it].x, wf.x, acc1[j]);
            acc1[j] = fmaf(xb[it].y, wf.y, acc1[j]);
            acc1[j] = fmaf(xb[it].z, wf.z, acc1[j]);
            acc1[j] = fmaf(xb[it].w, wf.w, acc1[j]);
        }
    }

    // warp butterfly reduce (20 values) -> smem
    #pragma unroll
    for (int j = 0; j < C_DIM; j++) {
        float v0 = acc0[j], v1 = acc1[j];
        #pragma unroll
        for (int off = 16; off; off >>= 1) {
            v0 += __shfl_xor_sync(0xffffffffu, v0, off);
            v1 += __shfl_xor_sync(0xffffffffu, v1, off);
        }
        if (lane == 0) {
            sAcc[warpId][j]          = v0;
            sAcc[warpId][C_DIM + j]  = v1;
        }
    }
    __syncthreads();

    float reg = 0.f;
    if (quarter == 0 && lane < R_ROWS) {
        // combine the 4 quarters for this row-pair; lane r handles row row0+r
        const float ALPHA = 1.0f - (float)C_DIM * NUM_STAB;
        float z[C_DIM];
        #pragma unroll
        for (int j = 0; j < C_DIM; j++) {
            float v = 0.f;
            #pragma unroll
            for (int q = 0; q < QUARTERS; q++)
                v += sAcc[q * 2 + rp][lane * C_DIM + j];
            z[j] = v;
        }

        float zmax = z[0];
        #pragma unroll
        for (int j = 1; j < C_DIM; j++) zmax = fmaxf(zmax, z[j]);

        float e[C_DIM], S = 0.f;
        #pragma unroll
        for (int j = 0; j < C_DIM; j++) { e[j] = expf(z[j] - zmax); S += e[j]; }
        const float invS = 1.f / S;

        float sig[C_DIM], p[C_DIM], s[C_DIM];
        float ssum = 0.f, psum_m = 0.f;
        #pragma unroll
        for (int j = 0; j < C_DIM; j++) {
            sig[j] = e[j] * invS;
            p[j]   = fmaf(ALPHA, sig[j], NUM_STAB);
            s[j]   = sqrtf(p[j]);
            ssum  += s[j];
            if (j < C_DIM - 1) psum_m += p[j];
        }
        const float sL = s[C_DIM - 1];
        const float t  = 1.f / (1.f - sL);

        float arg = ssum * 0.31622776601683794f;     // 1/sqrt(10)
        arg = fminf(1.f, fmaxf(-1.f, arg));
        const float delta = 2.f * acosf(arg);
        const float rho   = (2.f * (1.f - sL) - psum_m) * t;

        // v = M sigma, q = sigma^T M sigma
        float v[C_DIM], q = 0.f;
        #pragma unroll
        for (int k = 0; k < C_DIM; k++) {
            float a = 0.f;
            #pragma unroll
            for (int j = 0; j < C_DIM; j++)
                a = fmaf(sM[k * C_DIM + j], sig[j], a);
            v[k] = a;
            q = fmaf(sig[k], a, q);
        }

        // ||J||_F^2 = sum_i g_i^T M g_i,  g_i = a_i e_i + b_i e_L - (a_i+b_i) sigma
        const float gL = ALPHA * sig[C_DIM - 1] / sL;
        float fro = 0.f;
        #pragma unroll
        for (int i = 0; i < C_DIM - 1; i++) {
            float a = t * ALPHA * sig[i] / s[i];
            float b = s[i] * t * t * gL;
            float c = a + b;
            fro += a * a * sM[i * C_DIM + i]
                 + b * b * sM[C_DIM * C_DIM - 1]
                 + c * c * q
                 + 2.f * a * b * sM[i * C_DIM + (C_DIM - 1)]
                 - 2.f * c * (a * v[i] + b * v[C_DIM - 1]);
        }
        const float jac_norm = sqrtf(fmaxf(fro, 0.f));

        const float xv = jac_norm - delta / (rho * EPS_REG);
        reg = (xv > 0.f) ? xv : (expf(xv) - 1.f);
    }

    // deterministic block reduction (only warps 0,1 carry nonzero reg)
    #pragma unroll
    for (int off = 16; off; off >>= 1)
        reg += __shfl_xor_sync(0xffffffffu, reg, off);
    if (lane == 0) sWarpSum[warpId] = reg;
    __syncthreads();
    if (threadIdx.x == 0) {
        float ssum = 0.f;
        #pragma unroll
        for (int w = 0; w < WARPS; w++) ssum += sWarpSum[w];
        g_partials[blockIdx.x] = ssum;
        __threadfence();
        sIsLast = (atomicAdd(&g_count, 1u) == GRIDM - 1);
    }
    __syncthreads();

    // fused final reduction: last block sums all 1024 partials in fixed order
    if (sIsLast) {
        __threadfence();
        float v = 0.f;
        #pragma unroll
        for (int k = 0; k < GRIDM / BLOCK; k++)          // 4 strided chunks, fixed order
            v += g_partials[k * BLOCK + threadIdx.x];
        #pragma unroll
        for (int off = 16; off; off >>= 1)
            v += __shfl_xor_sync(0xffffffffu, v, off);
        if (lane == 0) sWarpSum[warpId] = v;
        __syncthreads();
        if (threadIdx.x == 0) {
            float ssum = 0.f;
            #pragma unroll
            for (int w = 0; w < WARPS; w++) ssum += sWarpSum[w];
            out[0] = ssum * (1.0f / (float)B_DIM);
            g_count = 0;                                  // reset for next graph replay
        }
    }
}

extern "C" void kernel_launch(void* const* d_in, const int* in_sizes, int n_in,
                              void* d_out, int out_size) {
    const float* data = (const float*)d_in[0];   // [4096, 3072] f32
    const float* W    = (const float*)d_in[1];   // [3072, 10]   f32
    float* out        = (float*)d_out;           // scalar f32

    prep_kernel<<<120, 256>>>(W);
    main_kernel<<<GRIDM, BLOCK>>>(data, out);
}

// round 6
// speedup vs baseline: 1.4190x; 1.4190x over previous
#include <cuda_runtime.h>
#include <math.h>

#define D_DIM 3072
#define C_DIM 10
#define B_DIM 4096
#define BLOCKS 148
#define WARPS 8
#define BLOCK 256
#define TOTW (BLOCKS * WARPS)            // 1184 warps
#define W4 (B_DIM - 3 * TOTW)            // 544 warps carry 4 rows, rest carry 3
#define NIT (D_DIM / 128)                // 24 tiles of 128 floats per row

#define EPS_REG 0.1f
#define NUM_STAB 1e-6f

// device scratch (no cudaMalloc allowed)
__device__ float g_M[C_DIM * C_DIM];
__device__ float g_partials[BLOCKS];
__device__ unsigned int g_Mdone = 0;
__device__ unsigned int g_count = 0;

// ---- packed fp32x2 (FFMA2) helpers ----
__device__ __forceinline__ unsigned long long ffma2(unsigned long long a,
                                                    unsigned long long b,
                                                    unsigned long long c) {
    unsigned long long d;
    asm("fma.rn.f32x2 %0, %1, %2, %3;" : "=l"(d) : "l"(a), "l"(b), "l"(c));
    return d;
}
__device__ __forceinline__ unsigned long long pk2(float a, float b) {
    unsigned long long r;
    asm("mov.b64 %0, {%1, %2};" : "=l"(r) : "f"(a), "f"(b));
    return r;
}
__device__ __forceinline__ float unpk_sum(unsigned long long v) {
    float lo, hi;
    asm("mov.b64 {%0, %1}, %2;" : "=f"(lo), "=f"(hi) : "l"(v));
    return lo + hi;
}

// ---- L2-scoped sync helpers (NO threadfence -> no L1 flush) ----
__device__ __forceinline__ void st_cg(float* p, float v) {
    asm volatile("st.cg.f32 [%0], %1;" :: "l"(p), "f"(v) : "memory");
}
__device__ __forceinline__ float ld_cg(const float* p) {
    float v;
    asm volatile("ld.cg.f32 %0, [%1];" : "=f"(v) : "l"(p) : "memory");
    return v;
}
__device__ __forceinline__ unsigned atom_add_release(unsigned* p, unsigned v) {
    unsigned old;
    asm volatile("atom.release.gpu.add.u32 %0, [%1], %2;"
                 : "=r"(old) : "l"(p), "r"(v) : "memory");
    return old;
}
__device__ __forceinline__ unsigned atom_add_acqrel(unsigned* p, unsigned v) {
    unsigned old;
    asm volatile("atom.acq_rel.gpu.add.u32 %0, [%1], %2;"
                 : "=r"(old) : "l"(p), "r"(v) : "memory");
    return old;
}
__device__ __forceinline__ unsigned ld_acquire(const unsigned* p) {
    unsigned v;
    asm volatile("ld.acquire.gpu.u32 %0, [%1];" : "=r"(v) : "l"(p) : "memory");
    return v;
}

// ---------------------------------------------------------------------------
// Single fused kernel. grid=148, block=256, 1 CTA/SM, W in dynamic smem.
// Warp g handles 4 rows (g<544) or 3 rows (row 4 clamped to a valid address).
// Blocks 0..99: warp 0 also computes one entry of M = W^T W from smem W.
// ---------------------------------------------------------------------------
extern __shared__ float smem[];   // [0,30720): W^T [C][D]; then sM[100]; sWarp[8]

__global__ __launch_bounds__(BLOCK, 1)
void jac_kernel(const float* __restrict__ data,
                const float* __restrict__ W,
                float* __restrict__ out) {
    float* sW    = smem;                       // 10 x 3072
    float* sM    = smem + C_DIM * D_DIM;       // 100
    float* sWarp = sM + C_DIM * C_DIM;         // 8
    __shared__ bool sIsLast;

    const int tid    = threadIdx.x;
    const int warpId = tid >> 5;
    const int lane   = tid & 31;

    // ---- stage W into smem, transposed: sW[j*D + d] = W[d*C + j] ----
    #pragma unroll
    for (int k = 0; k < (C_DIM * D_DIM) / BLOCK; k++) {
        int idx = k * BLOCK + tid;             // coalesced read of W
        int d = idx / C_DIM;
        int j = idx - d * C_DIM;
        sW[j * D_DIM + d] = W[idx];
    }
    __syncthreads();

    // ---- blocks 0..99: warp 0 computes M[pair] from smem W, publishes it ----
    if (blockIdx.x < C_DIM * C_DIM && warpId == 0) {
        const int j1 = blockIdx.x / C_DIM;
        const int j2 = blockIdx.x - j1 * C_DIM;
        float part = 0.f;
        #pragma unroll 8
        for (int d = lane; d < D_DIM; d += 32)
            part = fmaf(sW[j1 * D_DIM + d], sW[j2 * D_DIM + d], part);
        #pragma unroll
        for (int off = 16; off; off >>= 1)
            part += __shfl_xor_sync(0xffffffffu, part, off);
        if (lane == 0) {
            st_cg(&g_M[blockIdx.x], part);
            atom_add_release(&g_Mdone, 1u);
        }
    }

    // ---- row assignment for this warp ----
    const int g  = blockIdx.x * WARPS + warpId;           // 0..1183
    const int nr = (g < W4) ? 4 : 3;
    const int r0 = (g < W4) ? 4 * g : 3 * g + W4;

    const float* xp[4];
    #pragma unroll
    for (int r = 0; r < 4; r++) {
        int rr = r0 + ((r < nr) ? r : nr - 1);            // clamp dummy row
        xp[r] = data + (size_t)rr * D_DIM + lane * 4;
    }

    // ---- GEMM mainloop: z[r][j] = sum_d x[r][d] * W[d][j] ----
    unsigned long long acc[4][C_DIM];
    #pragma unroll
    for (int r = 0; r < 4; r++)
        #pragma unroll
        for (int j = 0; j < C_DIM; j++) acc[r][j] = 0ULL;

    float4 buf[2][4];
    #pragma unroll
    for (int r = 0; r < 4; r++)
        buf[0][r] = __ldcs(reinterpret_cast<const float4*>(xp[r]));
    #pragma unroll
    for (int r = 0; r < 4; r++)
        buf[1][r] = __ldcs(reinterpret_cast<const float4*>(xp[r] + 128));

    #pragma unroll 2
    for (int it = 0; it < NIT; it++) {
        const int cur = it & 1;
        unsigned long long xl[4], xh[4];
        #pragma unroll
        for (int r = 0; r < 4; r++) {
            xl[r] = pk2(buf[cur][r].x, buf[cur][r].y);
            xh[r] = pk2(buf[cur][r].z, buf[cur][r].w);
        }
        if (it + 2 < NIT) {
            #pragma unroll
            for (int r = 0; r < 4; r++)
                buf[cur][r] = __ldcs(reinterpret_cast<const float4*>(
                                  xp[r] + (it + 2) * 128));
        }
        const float* wrow = sW + it * 128 + lane * 4;
        #pragma unroll
        for (int j = 0; j < C_DIM; j++) {
            float4 wf = *reinterpret_cast<const float4*>(wrow + j * D_DIM);
            unsigned long long wl = pk2(wf.x, wf.y);
            unsigned long long wh = pk2(wf.z, wf.w);
            #pragma unroll
            for (int r = 0; r < 4; r++)
                acc[r][j] = ffma2(xh[r], wh, ffma2(xl[r], wl, acc[r][j]));
        }
    }

    // ---- warp butterfly reduce (all lanes end with the full sums) ----
    float accf[4][C_DIM];
    #pragma unroll
    for (int r = 0; r < 4; r++)
        #pragma unroll
        for (int j = 0; j < C_DIM; j++) {
            float v = unpk_sum(acc[r][j]);
            #pragma unroll
            for (int off = 16; off; off >>= 1)
                v += __shfl_xor_sync(0xffffffffu, v, off);
            accf[r][j] = v;
        }

    // ---- wait for M (long done by now), load into smem ----
    __syncthreads();
    if (tid == 0) {
        unsigned v = ld_acquire(&g_Mdone);
        while (v < C_DIM * C_DIM) { __nanosleep(64); v = ld_acquire(&g_Mdone); }
    }
    __syncthreads();
    if (tid < C_DIM * C_DIM) sM[tid] = ld_cg(&g_M[tid]);
    __syncthreads();

    // ---- analytic epilogue: lanes 0..nr-1 handle row r0+lane ----
    float reg = 0.f;
    if (lane < nr) {
        const float ALPHA = 1.0f - (float)C_DIM * NUM_STAB;
        float z[C_DIM];
        #pragma unroll
        for (int j = 0; j < C_DIM; j++) {
            float v = accf[0][j];
            v = (lane == 1) ? accf[1][j] : v;
            v = (lane == 2) ? accf[2][j] : v;
            v = (lane == 3) ? accf[3][j] : v;
            z[j] = v;
        }

        float zmax = z[0];
        #pragma unroll
        for (int j = 1; j < C_DIM; j++) zmax = fmaxf(zmax, z[j]);

        float e[C_DIM], S = 0.f;
        #pragma unroll
        for (int j = 0; j < C_DIM; j++) { e[j] = expf(z[j] - zmax); S += e[j]; }
        const float invS = 1.f / S;

        float sig[C_DIM], p[C_DIM], s[C_DIM];
        float ssum = 0.f, psum_m = 0.f;
        #pragma unroll
        for (int j = 0; j < C_DIM; j++) {
            sig[j] = e[j] * invS;
            p[j]   = fmaf(ALPHA, sig[j], NUM_STAB);
            s[j]   = sqrtf(p[j]);
            ssum  += s[j];
            if (j < C_DIM - 1) psum_m += p[j];
        }
        const float sL = s[C_DIM - 1];
        const float t  = 1.f / (1.f - sL);

        float arg = ssum * 0.31622776601683794f;          // 1/sqrt(10)
        arg = fminf(1.f, fmaxf(-1.f, arg));
        const float delta = 2.f * acosf(arg);
        const float rho   = (2.f * (1.f - sL) - psum_m) * t;

        // v = M sigma, q = sigma^T M sigma
        float v[C_DIM], q = 0.f;
        #pragma unroll
        for (int k = 0; k < C_DIM; k++) {
            float a = 0.f;
            #pragma unroll
            for (int j = 0; j < C_DIM; j++)
                a = fmaf(sM[k * C_DIM + j], sig[j], a);
            v[k] = a;
            q = fmaf(sig[k], a, q);
        }

        // ||J||_F^2 = sum_i g_i^T M g_i,  g_i = a_i e_i + b_i e_L - (a_i+b_i) sigma
        const float gL = ALPHA * sig[C_DIM - 1] / sL;
        float fro = 0.f;
        #pragma unroll
        for (int i = 0; i < C_DIM - 1; i++) {
            float a = t * ALPHA * sig[i] / s[i];
            float b = s[i] * t * t * gL;
            float c = a + b;
            fro += a * a * sM[i * C_DIM + i]
                 + b * b * sM[C_DIM * C_DIM - 1]
                 + c * c * q
                 + 2.f * a * b * sM[i * C_DIM + (C_DIM - 1)]
                 - 2.f * c * (a * v[i] + b * v[C_DIM - 1]);
        }
        const float jac_norm = sqrtf(fmaxf(fro, 0.f));

        const float xv = jac_norm - delta / (rho * EPS_REG);
        reg = (xv > 0.f) ? xv : (expf(xv) - 1.f);
    }

    // ---- deterministic block reduction ----
    #pragma unroll
    for (int off = 16; off; off >>= 1)
        reg += __shfl_xor_sync(0xffffffffu, reg, off);
    if (lane == 0) sWarp[warpId] = reg;
    __syncthreads();
    if (tid == 0) {
        float ssum = 0.f;
        #pragma unroll
        for (int w = 0; w < WARPS; w++) ssum += sWarp[w];
        st_cg(&g_partials[blockIdx.x], ssum);
        sIsLast = (atom_add_acqrel(&g_count, 1u) == BLOCKS - 1);
    }
    __syncthreads();

    // ---- fused final reduction by the last block (fixed order) ----
    if (sIsLast) {
        float v = (tid < BLOCKS) ? ld_cg(&g_partials[tid]) : 0.f;
        #pragma unroll
        for (int off = 16; off; off >>= 1)
            v += __shfl_xor_sync(0xffffffffu, v, off);
        if (lane == 0) sWarp[warpId] = v;
        __syncthreads();
        if (tid == 0) {
            float ssum = 0.f;
            #pragma unroll
            for (int w = 0; w < WARPS; w++) ssum += sWarp[w];
            out[0] = ssum * (1.0f / (float)B_DIM);
            // reset counters for next graph replay (all blocks have arrived)
            asm volatile("st.cg.u32 [%0], %1;" :: "l"(&g_count), "r"(0u) : "memory");
            asm volatile("st.cg.u32 [%0], %1;" :: "l"(&g_Mdone), "r"(0u) : "memory");
        }
    }
}

extern "C" void kernel_launch(void* const* d_in, const int* in_sizes, int n_in,
                              void* d_out, int out_size) {
    const float* data = (const float*)d_in[0];   // [4096, 3072] f32
    const float* W    = (const float*)d_in[1];   // [3072, 10]   f32
    float* out        = (float*)d_out;           // scalar f32

    const int smemBytes = (C_DIM * D_DIM + C_DIM * C_DIM + WARPS) * 4 + 128;
    cudaFuncSetAttribute(jac_kernel, cudaFuncAttributeMaxDynamicSharedMemorySize,
                         smemBytes);
    jac_kernel<<<BLOCKS, BLOCK, smemBytes>>>(data, W, out);
}